// round 13
// baseline (speedup 1.0000x reference)
#include <cuda_runtime.h>
#include <math.h>

#define BB 2
#define LL 320
#define DD 128
#define DP 64
#define NH 8
#define DH 16
#define DO 32
#define RPB 2                 // rows per block for row-fused kernels
#define NROW (BB*LL)          // 640
#define NPAIR (BB*LL*LL)      // 204800
#define SCP 321               // padded score row

// ---------------- scratch (allocation-free, device-side references ONLY) ----------------
__device__ float g_q [NROW*DD];
__device__ float g_k [NROW*DD];
__device__ float g_v [NROW*DD];
__device__ float g_bias[NPAIR*NH];     // [b,i,j,h]
__device__ float g_attn[NROW*DD];
__device__ float g_p1[NROW*DO];
__device__ float g_p2[NROW*DO];
__device__ float g_A [NROW*DO*DP];     // [row, d, p]

__device__ __forceinline__ float warp_sum(float v) {
    #pragma unroll
    for (int o = 16; o; o >>= 1) v += __shfl_xor_sync(0xffffffffu, v, o);
    return v;
}
__device__ __forceinline__ float warp_max(float v) {
    #pragma unroll
    for (int o = 16; o; o >>= 1) v = fmaxf(v, __shfl_xor_sync(0xffffffffu, v, o));
    return v;
}

// ---------------- fused ln1 + QKV: 2 rows/block, 512 threads ----------------
__global__ void __launch_bounds__(512)
ln1_qkv_kernel(const float* __restrict__ x,
               const float* __restrict__ lg, const float* __restrict__ lb,
               const float* __restrict__ Wq, const float* __restrict__ Wk,
               const float* __restrict__ Wv) {
    int r0 = blockIdx.x * RPB;
    int t = threadIdx.x;                 // 512
    __shared__ float xs[RPB][DD];
    __shared__ float r1[RPB][4], r2[RPB][4];
    if (t < RPB*DD) {
        int rr = t >> 7, cc = t & 127;
        float v = x[(r0 + rr)*DD + cc];
        float s = warp_sum(v);
        if ((t & 31) == 0) r1[rr][(cc >> 5)] = s;
        __syncwarp();
        xs[rr][cc] = v;                  // stash raw value
    }
    __syncthreads();
    if (t < RPB*DD) {
        int rr = t >> 7, cc = t & 127;
        float mu = (r1[rr][0] + r1[rr][1] + r1[rr][2] + r1[rr][3]) * (1.f/128.f);
        float d = xs[rr][cc] - mu;
        float sq = warp_sum(d*d);
        if ((t & 31) == 0) r2[rr][(cc >> 5)] = sq;
    }
    __syncthreads();
    if (t < RPB*DD) {
        int rr = t >> 7, cc = t & 127;
        float mu = (r1[rr][0] + r1[rr][1] + r1[rr][2] + r1[rr][3]) * (1.f/128.f);
        float var = (r2[rr][0] + r2[rr][1] + r2[rr][2] + r2[rr][3]) * (1.f/128.f);
        xs[rr][cc] = (xs[rr][cc] - mu) * rsqrtf(var + 1e-5f) * lg[cc] + lb[cc];
    }
    __syncthreads();
    if (t < 384) {
        int which = t >> 7, c = t & 127; // 0=q, 1=k, 2=v
        const float* W = (which == 0) ? Wq : ((which == 1) ? Wk : Wv);
        float* outp    = (which == 0) ? g_q : ((which == 1) ? g_k : g_v);
        float acc[RPB] = {0.f, 0.f};
        #pragma unroll 4
        for (int kk = 0; kk < DD; kk++) {
            float wv = W[kk*DD + c];
            #pragma unroll
            for (int r = 0; r < RPB; r++) acc[r] = fmaf(xs[r][kk], wv, acc[r]);
        }
        #pragma unroll
        for (int r = 0; r < RPB; r++) outp[(r0 + r)*DD + c] = acc[r];
    }
}

// ---------------- bias: smem-tiled, one (pair,h) output per thread ----------------
__global__ void bias_kernel(const float* __restrict__ z, const float* __restrict__ Wb) {
    __shared__ __align__(16) float zs[32][68];   // 32 pairs x 64 (+4 pad)
    __shared__ float wbs[DP][NH];                // [p][h]
    int t = threadIdx.x;                         // 256
    wbs[t >> 3][t & 7] = Wb[t];
    { int i2 = t + 256; wbs[i2 >> 3][i2 & 7] = Wb[i2]; }
    size_t base = (size_t)blockIdx.x * 32 * DP;
    const float4* zsrc = (const float4*)(z + base);
    #pragma unroll
    for (int i = 0; i < 2; i++) {
        int idx = t + i*256;
        int pair = idx >> 4, c4 = idx & 15;
        *((float4*)&zs[pair][c4*4]) = zsrc[idx];
    }
    __syncthreads();
    int pair = t >> 3, h = t & 7;
    float a0 = 0.f, a1 = 0.f;
    #pragma unroll
    for (int p = 0; p < DP; p += 2) {
        a0 = fmaf(zs[pair][p],   wbs[p][h],   a0);
        a1 = fmaf(zs[pair][p+1], wbs[p+1][h], a1);
    }
    g_bias[(size_t)blockIdx.x * 256 + t] = a0 + a1;
}

// ---------------- attention: one block per (b,i), V tiled via SMEM ----------------
__global__ void attn_kernel() {
    int bi = blockIdx.x;
    int b = bi / LL;
    int t = threadIdx.x;            // 256
    __shared__ float qs[DD];
    __shared__ float sc[NH*SCP];
    __shared__ float vs[32*DD];
    __shared__ float part[DD];
    if (t < DD) qs[t] = g_q[bi*DD + t];
    __syncthreads();
    for (int idx = t; idx < NH*LL; idx += 256) {
        int h = idx / LL, j = idx - h*LL;
        const float4* kp = (const float4*)(g_k + ((size_t)(b*LL + j))*DD + h*DH);
        const float4* qp = (const float4*)(qs + h*DH);
        float acc = 0.f;
        #pragma unroll
        for (int d4 = 0; d4 < 4; d4++) {
            float4 kv = kp[d4], qv = qp[d4];
            acc = fmaf(qv.x, kv.x, acc);
            acc = fmaf(qv.y, kv.y, acc);
            acc = fmaf(qv.z, kv.z, acc);
            acc = fmaf(qv.w, kv.w, acc);
        }
        sc[h*SCP + j] = acc * 0.25f + g_bias[((size_t)bi*LL + j)*NH + h];
    }
    __syncthreads();
    int w = t >> 5, lane = t & 31;
    float m = -INFINITY;
    for (int j = lane; j < LL; j += 32) m = fmaxf(m, sc[w*SCP + j]);
    m = warp_max(m);
    float s = 0.f;
    for (int j = lane; j < LL; j += 32) {
        float e = __expf(sc[w*SCP + j] - m);
        sc[w*SCP + j] = e;
        s += e;
    }
    s = warp_sum(s);
    float inv = 1.f / s;
    for (int j = lane; j < LL; j += 32) sc[w*SCP + j] *= inv;
    __syncthreads();
    int c = t & 127, half = t >> 7;
    int h = c >> 4;
    float acc = 0.f;
    int jb = half * 16;
    for (int j0 = 0; j0 < LL; j0 += 32) {
        const float4* vsrc = (const float4*)(g_v + ((size_t)(b*LL + j0))*DD);
        float4* vdst = (float4*)vs;
        #pragma unroll
        for (int i = 0; i < 4; i++) vdst[t + i*256] = vsrc[t + i*256];
        __syncthreads();
        #pragma unroll
        for (int jj = 0; jj < 16; jj++)
            acc = fmaf(sc[h*SCP + j0 + jb + jj], vs[(jb + jj)*DD + c], acc);
        __syncthreads();
    }
    if (half == 1) part[c] = acc;
    __syncthreads();
    if (half == 0) g_attn[bi*DD + c] = acc + part[c];
}

// ---------------- mega row kernel: proj + ln2 + ffn1 + ffn2 + pproj ----------------
// Smem-staged weights + vectorized LDS.128 reads (4 cols/thread, split-K partials
// aliased into the weight tile buffer after the last tile sync).
__global__ void __launch_bounds__(512)
mega_row_kernel(const float* __restrict__ x,
                const float* __restrict__ Wo, const float* __restrict__ bo,
                const float* __restrict__ lg2, const float* __restrict__ lb2,
                const float* __restrict__ W1, const float* __restrict__ b1,
                const float* __restrict__ W2, const float* __restrict__ b2,
                float* __restrict__ out_x,
                const float* __restrict__ Wp1, const float* __restrict__ bp1,
                const float* __restrict__ Wp2, const float* __restrict__ bp2) {
    int r0 = blockIdx.x * RPB;
    int t = threadIdx.x;   // 512
    __shared__ float as[RPB][DD];
    __shared__ float xs[RPB][DD];
    __shared__ float vres[RPB][DD];
    __shared__ float hs[RPB][512];
    __shared__ float r1[RPB][4], r2[RPB][4];
    __shared__ __align__(16) float ws[8192];    // 32 KB weight tile / split-K partials
    float* part = ws;                           // alias (used strictly after last tile read)

    if (t < RPB*DD) { int rr = t >> 7, cc = t & 127; as[rr][cc] = g_attn[(r0 + rr)*DD + cc]; }
    __syncthreads();

    // --- proj: out[2][128] = as @ Wo. 2 tiles of Wo[64][128]; 32 colgroups x 16 kslices ---
    {
        int cg = t & 31, ksl = t >> 5;     // cols 4cg..4cg+3; k rows ksl*4..+3 per tile
        float a00=0,a01=0,a02=0,a03=0, a10=0,a11=0,a12=0,a13=0;
        for (int kt = 0; kt < DD; kt += 64) {
            const float4* src = (const float4*)(Wo + kt*DD);
            float4* dst = (float4*)ws;
            #pragma unroll
            for (int i = 0; i < 4; i++) dst[t + i*512] = src[t + i*512];
            __syncthreads();
            #pragma unroll
            for (int kk = 0; kk < 4; kk++) {
                int k = ksl*4 + kk;
                float4 wv = *(const float4*)&ws[k*DD + cg*4];
                float x0 = as[0][kt+k], x1 = as[1][kt+k];
                a00 = fmaf(x0, wv.x, a00); a01 = fmaf(x0, wv.y, a01);
                a02 = fmaf(x0, wv.z, a02); a03 = fmaf(x0, wv.w, a03);
                a10 = fmaf(x1, wv.x, a10); a11 = fmaf(x1, wv.y, a11);
                a12 = fmaf(x1, wv.z, a12); a13 = fmaf(x1, wv.w, a13);
            }
            __syncthreads();
        }
        // partials -> ws alias: part[(ksl*2+r)*128 + col]
        *(float4*)&part[(ksl*RPB + 0)*DD + cg*4] = make_float4(a00,a01,a02,a03);
        *(float4*)&part[(ksl*RPB + 1)*DD + cg*4] = make_float4(a10,a11,a12,a13);
    }
    __syncthreads();

    // --- residual + ln2 ---
    if (t < RPB*DD) {
        int rr = t >> 7, cc = t & 127;
        float v = x[(r0+rr)*DD + cc] + bo[cc];
        #pragma unroll
        for (int k2 = 0; k2 < 16; k2++) v += part[(k2*RPB + rr)*DD + cc];
        vres[rr][cc] = v;
        float s = warp_sum(v);
        if ((t & 31) == 0) r1[rr][cc >> 5] = s;
    }
    __syncthreads();
    if (t < RPB*DD) {
        int rr = t >> 7, cc = t & 127;
        float mu = (r1[rr][0] + r1[rr][1] + r1[rr][2] + r1[rr][3]) * (1.f/128.f);
        float d = vres[rr][cc] - mu;
        float sq = warp_sum(d*d);
        if ((t & 31) == 0) r2[rr][cc >> 5] = sq;
    }
    __syncthreads();
    if (t < RPB*DD) {
        int rr = t >> 7, cc = t & 127;
        float mu = (r1[rr][0] + r1[rr][1] + r1[rr][2] + r1[rr][3]) * (1.f/128.f);
        float var = (r2[rr][0] + r2[rr][1] + r2[rr][2] + r2[rr][3]) * (1.f/128.f);
        xs[rr][cc] = (vres[rr][cc] - mu) * rsqrtf(var + 1e-5f) * lg2[cc] + lb2[cc];
    }
    __syncthreads();

    // --- ffn1: out[2][512]. 8 tiles of W1[16][512]; 128 colgroups x 4 kslices ---
    {
        int cg = t & 127, ksl = t >> 7;    // cols 4cg..4cg+3; k rows ksl*4..+3 per tile
        float a00=0,a01=0,a02=0,a03=0, a10=0,a11=0,a12=0,a13=0;
        for (int kt = 0; kt < DD; kt += 16) {
            const float4* src = (const float4*)(W1 + kt*512);
            float4* dst = (float4*)ws;
            #pragma unroll
            for (int i = 0; i < 4; i++) dst[t + i*512] = src[t + i*512];
            __syncthreads();
            #pragma unroll
            for (int kk = 0; kk < 4; kk++) {
                int k = ksl*4 + kk;
                float4 wv = *(const float4*)&ws[k*512 + cg*4];
                float x0 = xs[0][kt+k], x1 = xs[1][kt+k];
                a00 = fmaf(x0, wv.x, a00); a01 = fmaf(x0, wv.y, a01);
                a02 = fmaf(x0, wv.z, a02); a03 = fmaf(x0, wv.w, a03);
                a10 = fmaf(x1, wv.x, a10); a11 = fmaf(x1, wv.y, a11);
                a12 = fmaf(x1, wv.z, a12); a13 = fmaf(x1, wv.w, a13);
            }
            __syncthreads();
        }
        // part[(ksl*2+r)*512 + col]
        *(float4*)&part[(ksl*RPB + 0)*512 + cg*4] = make_float4(a00,a01,a02,a03);
        *(float4*)&part[(ksl*RPB + 1)*512 + cg*4] = make_float4(a10,a11,a12,a13);
    }
    __syncthreads();
    // reduce + bias + gelu -> hs
    {
        float bb = b1[t];
        #pragma unroll
        for (int r = 0; r < RPB; r++) {
            float v = bb;
            #pragma unroll
            for (int k2 = 0; k2 < 4; k2++) v += part[(k2*RPB + r)*512 + t];
            hs[r][t] = 0.5f * v * (1.f + erff(v * 0.70710678118654752f));
        }
    }
    __syncthreads();

    // --- ffn2: out[2][128]. 8 tiles of W2[64][128]; 32 colgroups x 16 kslices ---
    {
        int cg = t & 31, ksl = t >> 5;
        float a00=0,a01=0,a02=0,a03=0, a10=0,a11=0,a12=0,a13=0;
        for (int kt = 0; kt < 512; kt += 64) {
            const float4* src = (const float4*)(W2 + kt*DD);
            float4* dst = (float4*)ws;
            #pragma unroll
            for (int i = 0; i < 4; i++) dst[t + i*512] = src[t + i*512];
            __syncthreads();
            #pragma unroll
            for (int kk = 0; kk < 4; kk++) {
                int k = ksl*4 + kk;
                float4 wv = *(const float4*)&ws[k*DD + cg*4];
                float h0 = hs[0][kt+k], h1 = hs[1][kt+k];
                a00 = fmaf(h0, wv.x, a00); a01 = fmaf(h0, wv.y, a01);
                a02 = fmaf(h0, wv.z, a02); a03 = fmaf(h0, wv.w, a03);
                a10 = fmaf(h1, wv.x, a10); a11 = fmaf(h1, wv.y, a11);
                a12 = fmaf(h1, wv.z, a12); a13 = fmaf(h1, wv.w, a13);
            }
            __syncthreads();
        }
        *(float4*)&part[(ksl*RPB + 0)*DD + cg*4] = make_float4(a00,a01,a02,a03);
        *(float4*)&part[(ksl*RPB + 1)*DD + cg*4] = make_float4(a10,a11,a12,a13);
    }
    __syncthreads();
    if (t < RPB*DD) {
        int rr = t >> 7, cc = t & 127;
        float xv = vres[rr][cc] + b2[cc];
        #pragma unroll
        for (int k2 = 0; k2 < 16; k2++) xv += part[(k2*RPB + rr)*DD + cc];
        out_x[(r0+rr)*DD + cc] = xv;
        xs[rr][cc] = xv;
    }
    __syncthreads();

    // --- pproj: 64 outputs (32 p1 + 32 p2), split-K4 (reuse part region past 4096) ---
    {
        float* pp = ws + 4096;     // disjoint from nothing now; weights done
        if (t < 256) {
            int o  = t & 63;       // 0..31 -> p1, 32..63 -> p2
            int sl = t >> 6;       // 0..3
            const float* W = (o < 32) ? Wp1 : Wp2;
            int col = o & 31;
            int k0 = sl*32;
            float acc[RPB] = {0.f, 0.f};
            #pragma unroll
            for (int kk = 0; kk < 32; kk++) {
                float wv = W[(k0+kk)*DO + col];
                #pragma unroll
                for (int r = 0; r < RPB; r++) acc[r] = fmaf(xs[r][k0+kk], wv, acc[r]);
            }
            #pragma unroll
            for (int r = 0; r < RPB; r++) pp[(sl*RPB + r)*64 + o] = acc[r];
        }
        __syncthreads();
        if (t < RPB*64) {          // 2 rows x 64 outputs
            int r = t >> 6, o = t & 63;
            float sum = pp[(0*RPB+r)*64+o] + pp[(1*RPB+r)*64+o]
                      + pp[(2*RPB+r)*64+o] + pp[(3*RPB+r)*64+o];
            if (o < 32) g_p1[(r0+r)*DO + o]        = sum + bp1[o];
            else        g_p2[(r0+r)*DO + (o - 32)] = sum + bp2[o - 32];
        }
    }
}

// ---------------- A[row, d, p]: grid = (NROW/4) x 4 dp-chunks for occupancy ----------------
__global__ void a_kernel(const float* __restrict__ Wz) {
    int blk = blockIdx.x;
    int r0  = (blk >> 2) * 4;          // 4 rows
    int dp0 = (blk & 3) * 512;         // 512-wide dp chunk
    int t = threadIdx.x;               // 256
    __shared__ float p1s[4][DO];
    if (t < 128) { int r = t >> 5, c = t & 31; p1s[r][c] = g_p1[(r0 + r)*DO + c]; }
    __syncthreads();
    #pragma unroll
    for (int i = 0; i < 2; i++) {
        int dp = dp0 + t + i*256;
        float acc[4] = {0,0,0,0};
        #pragma unroll 8
        for (int c = 0; c < DO; c++) {
            float wv = Wz[(size_t)c*(DO*DP) + dp];
            #pragma unroll
            for (int r = 0; r < 4; r++) acc[r] = fmaf(p1s[r][c], wv, acc[r]);
        }
        #pragma unroll
        for (int r = 0; r < 4; r++) g_A[(size_t)(r0 + r)*(DO*DP) + dp] = acc[r];
    }
}

// ---------------- final: z_out = LN(z + A(i)·p2(j) + bz), single j-row per warp iter ----------------
__global__ void __launch_bounds__(256, 2)
pair_final_kernel(const float* __restrict__ z, const float* __restrict__ bz,
                  const float* __restrict__ g, const float* __restrict__ be,
                  float* __restrict__ zout) {
    int bi = blockIdx.x;
    int b = bi / LL;
    int t = threadIdx.x, w = t >> 5, lane = t & 31;
    __shared__ __align__(16) float p2s[64][DO];   // 8 KB tile
    const float2* Ag = (const float2*)(g_A + (size_t)bi*(DO*DP));
    float2 a[DO];
    #pragma unroll
    for (int d = 0; d < DO; d++) a[d] = Ag[d*32 + lane];
    float bz0 = bz[2*lane], bz1 = bz[2*lane + 1];
    float g0 = g[2*lane],  g1 = g[2*lane + 1];
    float e0 = be[2*lane], e1 = be[2*lane + 1];
    size_t zbase = (size_t)bi * LL * DP;
    const float* p2b = g_p2 + (size_t)b * LL * DO;
    for (int jt = 0; jt < LL; jt += 64) {
        const float4* src = (const float4*)(p2b + (size_t)jt * DO);
        float4* dst = (float4*)&p2s[0][0];
        dst[t] = src[t];
        dst[t + 256] = src[t + 256];
        __syncthreads();
        for (int jj = w; jj < 64; jj += 8) {
            int j = jt + jj;
            float2 zv = *(const float2*)(z + zbase + (size_t)j*DP + 2*lane);
            const float4* p4 = (const float4*)&p2s[jj][0];
            float acc0 = 0.f, acc1 = 0.f;
            #pragma unroll
            for (int d4 = 0; d4 < 8; d4++) {
                float4 s4 = p4[d4];
                acc0 = fmaf(s4.x, a[d4*4+0].x, acc0); acc1 = fmaf(s4.x, a[d4*4+0].y, acc1);
                acc0 = fmaf(s4.y, a[d4*4+1].x, acc0); acc1 = fmaf(s4.y, a[d4*4+1].y, acc1);
                acc0 = fmaf(s4.z, a[d4*4+2].x, acc0); acc1 = fmaf(s4.z, a[d4*4+2].y, acc1);
                acc0 = fmaf(s4.w, a[d4*4+3].x, acc0); acc1 = fmaf(s4.w, a[d4*4+3].y, acc1);
            }
            float v0 = zv.x + acc0 + bz0;
            float v1 = zv.y + acc1 + bz1;
            float s1 = warp_sum(v0 + v1);
            float s2 = warp_sum(fmaf(v0, v0, v1*v1));
            float mu = s1 * (1.f/64.f);
            float var = s2 * (1.f/64.f) - mu*mu;
            float rs = rsqrtf(var + 1e-5f);
            float2 o;
            o.x = (v0 - mu) * rs * g0 + e0;
            o.y = (v1 - mu) * rs * g1 + e1;
            *(float2*)(zout + zbase + (size_t)j*DP + 2*lane) = o;
        }
        __syncthreads();
    }
}

extern "C" void kernel_launch(void* const* d_in, const int* in_sizes, int n_in,
                              void* d_out, int out_size) {
    const float* x      = (const float*)d_in[0];
    const float* z      = (const float*)d_in[1];
    const float* Wq     = (const float*)d_in[2];
    const float* Wk     = (const float*)d_in[3];
    const float* Wv     = (const float*)d_in[4];
    const float* Wb     = (const float*)d_in[5];
    const float* Wo     = (const float*)d_in[6];
    const float* bo     = (const float*)d_in[7];
    const float* ln1_g  = (const float*)d_in[8];
    const float* ln1_b  = (const float*)d_in[9];
    const float* W1     = (const float*)d_in[10];
    const float* b1     = (const float*)d_in[11];
    const float* W2     = (const float*)d_in[12];
    const float* b2     = (const float*)d_in[13];
    const float* ln2_g  = (const float*)d_in[14];
    const float* ln2_b  = (const float*)d_in[15];
    const float* Wp1    = (const float*)d_in[16];
    const float* bp1    = (const float*)d_in[17];
    const float* Wp2    = (const float*)d_in[18];
    const float* bp2    = (const float*)d_in[19];
    const float* Wz     = (const float*)d_in[20];
    const float* bz     = (const float*)d_in[21];
    const float* lnp_g  = (const float*)d_in[22];
    const float* lnp_b  = (const float*)d_in[23];

    float* out_x = (float*)d_out;                       // [B,L,D]
    float* out_z = (float*)d_out + (size_t)NROW*DD;     // [B,L,L,DP]

    ln1_qkv_kernel<<<NROW/RPB, 512>>>(x, ln1_g, ln1_b, Wq, Wk, Wv);
    bias_kernel<<<NPAIR/32, 256>>>(z, Wb);
    attn_kernel<<<NROW, 256>>>();
    mega_row_kernel<<<NROW/RPB, 512>>>(x, Wo, bo, ln2_g, ln2_b, W1, b1, W2, b2,
                                       out_x, Wp1, bp1, Wp2, bp2);
    a_kernel<<<(NROW/4)*4, 256>>>(Wz);
    pair_final_kernel<<<NROW, 256>>>(z, bz, lnp_g, lnp_b, out_z);
}

// round 14
// speedup vs baseline: 1.0060x; 1.0060x over previous
#include <cuda_runtime.h>
#include <math.h>

#define BB 2
#define LL 320
#define DD 128
#define DP 64
#define NH 8
#define DH 16
#define DO 32
#define RPB 2                 // rows per block for row-fused kernels
#define NROW (BB*LL)          // 640
#define NPAIR (BB*LL*LL)      // 204800
#define SCP 321               // padded score row

// ---------------- scratch (allocation-free, device-side references ONLY) ----------------
__device__ float g_q [NROW*DD];
__device__ float g_k [NROW*DD];
__device__ float g_v [NROW*DD];
__device__ float g_bias[NPAIR*NH];     // [b,i,j,h]
__device__ float g_attn[NROW*DD];
__device__ float g_p1[NROW*DO];
__device__ float g_p2[NROW*DO];
__device__ float g_A [NROW*DO*DP];     // [row, d, p]

__device__ __forceinline__ float warp_sum(float v) {
    #pragma unroll
    for (int o = 16; o; o >>= 1) v += __shfl_xor_sync(0xffffffffu, v, o);
    return v;
}
__device__ __forceinline__ float warp_max(float v) {
    #pragma unroll
    for (int o = 16; o; o >>= 1) v = fmaxf(v, __shfl_xor_sync(0xffffffffu, v, o));
    return v;
}

// ---------------- fused ln1 + QKV: 2 rows/block, 512 threads ----------------
__global__ void __launch_bounds__(512)
ln1_qkv_kernel(const float* __restrict__ x,
               const float* __restrict__ lg, const float* __restrict__ lb,
               const float* __restrict__ Wq, const float* __restrict__ Wk,
               const float* __restrict__ Wv) {
    int r0 = blockIdx.x * RPB;
    int t = threadIdx.x;                 // 512
    __shared__ float xs[RPB][DD];
    __shared__ float r1[RPB][4], r2[RPB][4];
    if (t < RPB*DD) {
        int rr = t >> 7, cc = t & 127;
        float v = x[(r0 + rr)*DD + cc];
        float s = warp_sum(v);
        if ((t & 31) == 0) r1[rr][(cc >> 5)] = s;
        __syncwarp();
        xs[rr][cc] = v;                  // stash raw value
    }
    __syncthreads();
    if (t < RPB*DD) {
        int rr = t >> 7, cc = t & 127;
        float mu = (r1[rr][0] + r1[rr][1] + r1[rr][2] + r1[rr][3]) * (1.f/128.f);
        float d = xs[rr][cc] - mu;
        float sq = warp_sum(d*d);
        if ((t & 31) == 0) r2[rr][(cc >> 5)] = sq;
    }
    __syncthreads();
    if (t < RPB*DD) {
        int rr = t >> 7, cc = t & 127;
        float mu = (r1[rr][0] + r1[rr][1] + r1[rr][2] + r1[rr][3]) * (1.f/128.f);
        float var = (r2[rr][0] + r2[rr][1] + r2[rr][2] + r2[rr][3]) * (1.f/128.f);
        xs[rr][cc] = (xs[rr][cc] - mu) * rsqrtf(var + 1e-5f) * lg[cc] + lb[cc];
    }
    __syncthreads();
    if (t < 384) {
        int which = t >> 7, c = t & 127; // 0=q, 1=k, 2=v
        const float* W = (which == 0) ? Wq : ((which == 1) ? Wk : Wv);
        float* outp    = (which == 0) ? g_q : ((which == 1) ? g_k : g_v);
        float acc[RPB] = {0.f, 0.f};
        #pragma unroll 4
        for (int kk = 0; kk < DD; kk++) {
            float wv = W[kk*DD + c];
            #pragma unroll
            for (int r = 0; r < RPB; r++) acc[r] = fmaf(xs[r][kk], wv, acc[r]);
        }
        #pragma unroll
        for (int r = 0; r < RPB; r++) outp[(r0 + r)*DD + c] = acc[r];
    }
}

// ---------------- bias: smem-tiled, one (pair,h) output per thread ----------------
__global__ void bias_kernel(const float* __restrict__ z, const float* __restrict__ Wb) {
    __shared__ __align__(16) float zs[32][68];   // 32 pairs x 64 (+4 pad)
    __shared__ float wbs[DP][NH];                // [p][h]
    int t = threadIdx.x;                         // 256
    wbs[t >> 3][t & 7] = Wb[t];
    { int i2 = t + 256; wbs[i2 >> 3][i2 & 7] = Wb[i2]; }
    size_t base = (size_t)blockIdx.x * 32 * DP;
    const float4* zsrc = (const float4*)(z + base);
    #pragma unroll
    for (int i = 0; i < 2; i++) {
        int idx = t + i*256;
        int pair = idx >> 4, c4 = idx & 15;
        *((float4*)&zs[pair][c4*4]) = zsrc[idx];
    }
    __syncthreads();
    int pair = t >> 3, h = t & 7;
    float a0 = 0.f, a1 = 0.f;
    #pragma unroll
    for (int p = 0; p < DP; p += 2) {
        a0 = fmaf(zs[pair][p],   wbs[p][h],   a0);
        a1 = fmaf(zs[pair][p+1], wbs[p+1][h], a1);
    }
    g_bias[(size_t)blockIdx.x * 256 + t] = a0 + a1;
}

// ---------------- attention: one block per (b,i), V tiled via SMEM ----------------
__global__ void attn_kernel() {
    int bi = blockIdx.x;
    int b = bi / LL;
    int t = threadIdx.x;            // 256
    __shared__ float qs[DD];
    __shared__ float sc[NH*SCP];
    __shared__ float vs[32*DD];
    __shared__ float part[DD];
    if (t < DD) qs[t] = g_q[bi*DD + t];
    __syncthreads();
    for (int idx = t; idx < NH*LL; idx += 256) {
        int h = idx / LL, j = idx - h*LL;
        const float4* kp = (const float4*)(g_k + ((size_t)(b*LL + j))*DD + h*DH);
        const float4* qp = (const float4*)(qs + h*DH);
        float acc = 0.f;
        #pragma unroll
        for (int d4 = 0; d4 < 4; d4++) {
            float4 kv = kp[d4], qv = qp[d4];
            acc = fmaf(qv.x, kv.x, acc);
            acc = fmaf(qv.y, kv.y, acc);
            acc = fmaf(qv.z, kv.z, acc);
            acc = fmaf(qv.w, kv.w, acc);
        }
        sc[h*SCP + j] = acc * 0.25f + g_bias[((size_t)bi*LL + j)*NH + h];
    }
    __syncthreads();
    int w = t >> 5, lane = t & 31;
    float m = -INFINITY;
    for (int j = lane; j < LL; j += 32) m = fmaxf(m, sc[w*SCP + j]);
    m = warp_max(m);
    float s = 0.f;
    for (int j = lane; j < LL; j += 32) {
        float e = __expf(sc[w*SCP + j] - m);
        sc[w*SCP + j] = e;
        s += e;
    }
    s = warp_sum(s);
    float inv = 1.f / s;
    for (int j = lane; j < LL; j += 32) sc[w*SCP + j] *= inv;
    __syncthreads();
    int c = t & 127, half = t >> 7;
    int h = c >> 4;
    float acc = 0.f;
    int jb = half * 16;
    for (int j0 = 0; j0 < LL; j0 += 32) {
        const float4* vsrc = (const float4*)(g_v + ((size_t)(b*LL + j0))*DD);
        float4* vdst = (float4*)vs;
        #pragma unroll
        for (int i = 0; i < 4; i++) vdst[t + i*256] = vsrc[t + i*256];
        __syncthreads();
        #pragma unroll
        for (int jj = 0; jj < 16; jj++)
            acc = fmaf(sc[h*SCP + j0 + jb + jj], vs[(jb + jj)*DD + c], acc);
        __syncthreads();
    }
    if (half == 1) part[c] = acc;
    __syncthreads();
    if (half == 0) g_attn[bi*DD + c] = acc + part[c];
}

// ---------------- mega row kernel: proj + ln2 + ffn1 + ffn2 + pproj ----------------
// (round-12 proven version: smem-staged weights, scalar LDS reads)
__global__ void __launch_bounds__(512)
mega_row_kernel(const float* __restrict__ x,
                const float* __restrict__ Wo, const float* __restrict__ bo,
                const float* __restrict__ lg2, const float* __restrict__ lb2,
                const float* __restrict__ W1, const float* __restrict__ b1,
                const float* __restrict__ W2, const float* __restrict__ b2,
                float* __restrict__ out_x,
                const float* __restrict__ Wp1, const float* __restrict__ bp1,
                const float* __restrict__ Wp2, const float* __restrict__ bp2) {
    int r0 = blockIdx.x * RPB;
    int t = threadIdx.x;   // 512
    __shared__ float as[RPB][DD];
    __shared__ float xs[RPB][DD];
    __shared__ float vres[RPB][DD];
    __shared__ float hs[RPB][512];
    __shared__ float part[4][RPB][DD];
    __shared__ float r1[RPB][4], r2[RPB][4];
    __shared__ __align__(16) float ws[8192];    // 32 KB weight tile

    if (t < RPB*DD) { int rr = t >> 7, cc = t & 127; as[rr][cc] = g_attn[(r0 + rr)*DD + cc]; }
    __syncthreads();

    int c = t & 127, ks = t >> 7;            // ks 0..3

    // --- proj: 2 smem tiles of Wo[64][128], split-K4 within tile ---
    {
        float acc[RPB] = {0.f, 0.f};
        for (int kt = 0; kt < DD; kt += 64) {
            const float4* src = (const float4*)(Wo + kt*DD);
            float4* dst = (float4*)ws;
            #pragma unroll
            for (int i = 0; i < 4; i++) dst[t + i*512] = src[t + i*512];
            __syncthreads();
            int k0 = ks*16;
            #pragma unroll
            for (int kk = 0; kk < 16; kk++) {
                float wv = ws[(k0+kk)*DD + c];
                #pragma unroll
                for (int r = 0; r < RPB; r++) acc[r] = fmaf(as[r][kt+k0+kk], wv, acc[r]);
            }
            __syncthreads();
        }
        #pragma unroll
        for (int r = 0; r < RPB; r++) part[ks][r][c] = acc[r];
    }
    __syncthreads();

    // --- residual + ln2 (first 256 threads = 2 rows x 128 cols) ---
    if (t < RPB*DD) {
        int rr = t >> 7, cc = t & 127;
        float v = x[(r0+rr)*DD + cc] + part[0][rr][cc] + part[1][rr][cc]
                + part[2][rr][cc] + part[3][rr][cc] + bo[cc];
        vres[rr][cc] = v;
        float s = warp_sum(v);
        if ((t & 31) == 0) r1[rr][cc >> 5] = s;
    }
    __syncthreads();
    if (t < RPB*DD) {
        int rr = t >> 7, cc = t & 127;
        float mu = (r1[rr][0] + r1[rr][1] + r1[rr][2] + r1[rr][3]) * (1.f/128.f);
        float d = vres[rr][cc] - mu;
        float sq = warp_sum(d*d);
        if ((t & 31) == 0) r2[rr][cc >> 5] = sq;
    }
    __syncthreads();
    if (t < RPB*DD) {
        int rr = t >> 7, cc = t & 127;
        float mu = (r1[rr][0] + r1[rr][1] + r1[rr][2] + r1[rr][3]) * (1.f/128.f);
        float var = (r2[rr][0] + r2[rr][1] + r2[rr][2] + r2[rr][3]) * (1.f/128.f);
        xs[rr][cc] = (vres[rr][cc] - mu) * rsqrtf(var + 1e-5f) * lg2[cc] + lb2[cc];
    }
    __syncthreads();

    // --- ffn1: 8 smem tiles of W1[16][512], one output col per thread ---
    {
        float acc[RPB] = {0.f, 0.f};
        for (int kt = 0; kt < DD; kt += 16) {
            const float4* src = (const float4*)(W1 + kt*512);
            float4* dst = (float4*)ws;
            #pragma unroll
            for (int i = 0; i < 4; i++) dst[t + i*512] = src[t + i*512];
            __syncthreads();
            #pragma unroll
            for (int kk = 0; kk < 16; kk++) {
                float wv = ws[kk*512 + t];
                #pragma unroll
                for (int r = 0; r < RPB; r++) acc[r] = fmaf(xs[r][kt+kk], wv, acc[r]);
            }
            __syncthreads();
        }
        float bb = b1[t];
        #pragma unroll
        for (int r = 0; r < RPB; r++) {
            float hv = acc[r] + bb;
            hs[r][t] = 0.5f * hv * (1.f + erff(hv * 0.70710678118654752f));
        }
    }
    __syncthreads();

    // --- ffn2: 8 smem tiles of W2[64][128], split-K4 within tile ---
    {
        float acc[RPB] = {0.f, 0.f};
        for (int kt = 0; kt < 512; kt += 64) {
            const float4* src = (const float4*)(W2 + kt*DD);
            float4* dst = (float4*)ws;
            #pragma unroll
            for (int i = 0; i < 4; i++) dst[t + i*512] = src[t + i*512];
            __syncthreads();
            int k0 = ks*16;
            #pragma unroll
            for (int kk = 0; kk < 16; kk++) {
                float wv = ws[(k0+kk)*DD + c];
                #pragma unroll
                for (int r = 0; r < RPB; r++) acc[r] = fmaf(hs[r][kt+k0+kk], wv, acc[r]);
            }
            __syncthreads();
        }
        #pragma unroll
        for (int r = 0; r < RPB; r++) part[ks][r][c] = acc[r];
    }
    __syncthreads();
    if (t < RPB*DD) {
        int rr = t >> 7, cc = t & 127;
        float xv = vres[rr][cc] + part[0][rr][cc] + part[1][rr][cc]
                 + part[2][rr][cc] + part[3][rr][cc] + b2[cc];
        out_x[(r0+rr)*DD + cc] = xv;
        xs[rr][cc] = xv;
    }
    __syncthreads();

    // --- pproj: 64 outputs (32 p1 + 32 p2), split-K4 ---
    if (t < 256) {
        int o  = t & 63;           // 0..31 -> p1, 32..63 -> p2
        int sl = t >> 6;           // 0..3
        const float* W = (o < 32) ? Wp1 : Wp2;
        int col = o & 31;
        int k0 = sl*32;
        float acc[RPB] = {0.f, 0.f};
        #pragma unroll
        for (int kk = 0; kk < 32; kk++) {
            float wv = W[(k0+kk)*DO + col];
            #pragma unroll
            for (int r = 0; r < RPB; r++) acc[r] = fmaf(xs[r][k0+kk], wv, acc[r]);
        }
        #pragma unroll
        for (int r = 0; r < RPB; r++) part[sl][r][o] = acc[r];
    }
    __syncthreads();
    if (t < RPB*64) {              // 2 rows x 64 outputs
        int r = t >> 6, o = t & 63;
        float sum = part[0][r][o] + part[1][r][o] + part[2][r][o] + part[3][r][o];
        if (o < 32) g_p1[(r0+r)*DO + o]        = sum + bp1[o];
        else        g_p2[(r0+r)*DO + (o - 32)] = sum + bp2[o - 32];
    }
}

// ---------------- A[row, d, p]: grid = (NROW/4) x 4 dp-chunks for occupancy ----------------
__global__ void a_kernel(const float* __restrict__ Wz) {
    int blk = blockIdx.x;
    int r0  = (blk >> 2) * 4;          // 4 rows
    int dp0 = (blk & 3) * 512;         // 512-wide dp chunk
    int t = threadIdx.x;               // 256
    __shared__ float p1s[4][DO];
    if (t < 128) { int r = t >> 5, c = t & 31; p1s[r][c] = g_p1[(r0 + r)*DO + c]; }
    __syncthreads();
    #pragma unroll
    for (int i = 0; i < 2; i++) {
        int dp = dp0 + t + i*256;
        float acc[4] = {0,0,0,0};
        #pragma unroll 8
        for (int c = 0; c < DO; c++) {
            float wv = Wz[(size_t)c*(DO*DP) + dp];
            #pragma unroll
            for (int r = 0; r < 4; r++) acc[r] = fmaf(p1s[r][c], wv, acc[r]);
        }
        #pragma unroll
        for (int r = 0; r < 4; r++) g_A[(size_t)(r0 + r)*(DO*DP) + dp] = acc[r];
    }
}

// ---------------- final: z_out = LN(z + A(i)·p2(j) + bz) ----------------
// A in registers; p2 staged in smem tiles; z DOUBLE-BUFFERED across iterations
// so the DRAM load latency overlaps the previous iteration's FMA+reduction.
__global__ void __launch_bounds__(256, 2)
pair_final_kernel(const float* __restrict__ z, const float* __restrict__ bz,
                  const float* __restrict__ g, const float* __restrict__ be,
                  float* __restrict__ zout) {
    int bi = blockIdx.x;
    int b = bi / LL;
    int t = threadIdx.x, w = t >> 5, lane = t & 31;
    __shared__ __align__(16) float p2s[64][DO];   // 8 KB tile
    const float2* Ag = (const float2*)(g_A + (size_t)bi*(DO*DP));
    float2 a[DO];
    #pragma unroll
    for (int d = 0; d < DO; d++) a[d] = Ag[d*32 + lane];
    float bz0 = bz[2*lane], bz1 = bz[2*lane + 1];
    float g0 = g[2*lane],  g1 = g[2*lane + 1];
    float e0 = be[2*lane], e1 = be[2*lane + 1];
    size_t zbase = (size_t)bi * LL * DP;
    const float* p2b = g_p2 + (size_t)b * LL * DO;

    // per-warp deterministic j schedule: idx=0..39 -> tile=idx/8, j=tile*64 + w + (idx%8)*8
    const int NIT = (LL/64) * 8;                 // 40 iterations per warp
    // stage tile 0
    {
        const float4* src = (const float4*)p2b;
        float4* dst = (float4*)&p2s[0][0];
        dst[t] = src[t];
        dst[t + 256] = src[t + 256];
    }
    __syncthreads();

    int j0 = w;                                  // first j for this warp
    float2 zv_next = *(const float2*)(z + zbase + (size_t)j0*DP + 2*lane);

    for (int idx = 0; idx < NIT; idx++) {
        int tile = idx >> 3;
        int jj = w + ((idx & 7) << 3);           // row within tile
        int j = tile*64 + jj;
        float2 zv = zv_next;
        // prefetch next iteration's z (crosses tile boundaries safely — pure global read)
        if (idx + 1 < NIT) {
            int nidx = idx + 1;
            int nj = (nidx >> 3)*64 + w + ((nidx & 7) << 3);
            zv_next = *(const float2*)(z + zbase + (size_t)nj*DP + 2*lane);
        }
        const float4* p4 = (const float4*)&p2s[jj][0];
        float acc0 = 0.f, acc1 = 0.f;
        #pragma unroll
        for (int d4 = 0; d4 < 8; d4++) {
            float4 s4 = p4[d4];
            acc0 = fmaf(s4.x, a[d4*4+0].x, acc0); acc1 = fmaf(s4.x, a[d4*4+0].y, acc1);
            acc0 = fmaf(s4.y, a[d4*4+1].x, acc0); acc1 = fmaf(s4.y, a[d4*4+1].y, acc1);
            acc0 = fmaf(s4.z, a[d4*4+2].x, acc0); acc1 = fmaf(s4.z, a[d4*4+2].y, acc1);
            acc0 = fmaf(s4.w, a[d4*4+3].x, acc0); acc1 = fmaf(s4.w, a[d4*4+3].y, acc1);
        }
        float v0 = zv.x + acc0 + bz0;
        float v1 = zv.y + acc1 + bz1;
        float s1 = warp_sum(v0 + v1);
        float s2 = warp_sum(fmaf(v0, v0, v1*v1));
        float mu = s1 * (1.f/64.f);
        float var = s2 * (1.f/64.f) - mu*mu;
        float rs = rsqrtf(var + 1e-5f);
        float2 o;
        o.x = (v0 - mu) * rs * g0 + e0;
        o.y = (v1 - mu) * rs * g1 + e1;
        *(float2*)(zout + zbase + (size_t)j*DP + 2*lane) = o;

        // tile boundary: restage p2 for next tile
        if ((idx & 7) == 7 && tile + 1 < LL/64) {
            __syncthreads();
            const float4* src = (const float4*)(p2b + (size_t)(tile+1)*64*DO);
            float4* dst = (float4*)&p2s[0][0];
            dst[t] = src[t];
            dst[t + 256] = src[t + 256];
            __syncthreads();
        }
    }
}

extern "C" void kernel_launch(void* const* d_in, const int* in_sizes, int n_in,
                              void* d_out, int out_size) {
    const float* x      = (const float*)d_in[0];
    const float* z      = (const float*)d_in[1];
    const float* Wq     = (const float*)d_in[2];
    const float* Wk     = (const float*)d_in[3];
    const float* Wv     = (const float*)d_in[4];
    const float* Wb     = (const float*)d_in[5];
    const float* Wo     = (const float*)d_in[6];
    const float* bo     = (const float*)d_in[7];
    const float* ln1_g  = (const float*)d_in[8];
    const float* ln1_b  = (const float*)d_in[9];
    const float* W1     = (const float*)d_in[10];
    const float* b1     = (const float*)d_in[11];
    const float* W2     = (const float*)d_in[12];
    const float* b2     = (const float*)d_in[13];
    const float* ln2_g  = (const float*)d_in[14];
    const float* ln2_b  = (const float*)d_in[15];
    const float* Wp1    = (const float*)d_in[16];
    const float* bp1    = (const float*)d_in[17];
    const float* Wp2    = (const float*)d_in[18];
    const float* bp2    = (const float*)d_in[19];
    const float* Wz     = (const float*)d_in[20];
    const float* bz     = (const float*)d_in[21];
    const float* lnp_g  = (const float*)d_in[22];
    const float* lnp_b  = (const float*)d_in[23];

    float* out_x = (float*)d_out;                       // [B,L,D]
    float* out_z = (float*)d_out + (size_t)NROW*DD;     // [B,L,L,DP]

    ln1_qkv_kernel<<<NROW/RPB, 512>>>(x, ln1_g, ln1_b, Wq, Wk, Wv);
    bias_kernel<<<NPAIR/32, 256>>>(z, Wb);
    attn_kernel<<<NROW, 256>>>();
    mega_row_kernel<<<NROW/RPB, 512>>>(x, Wo, bo, ln2_g, ln2_b, W1, b1, W2, b2,
                                       out_x, Wp1, bp1, Wp2, bp2);
    a_kernel<<<(NROW/4)*4, 256>>>(Wz);
    pair_final_kernel<<<NROW, 256>>>(z, bz, lnp_g, lnp_b, out_z);
}

// round 15
// speedup vs baseline: 1.1031x; 1.0965x over previous
#include <cuda_runtime.h>
#include <math.h>

#define BB 2
#define LL 320
#define DD 128
#define DP 64
#define NH 8
#define DH 16
#define DO 32
#define RPB 2                 // rows per block for row-fused kernels
#define NROW (BB*LL)          // 640
#define NPAIR (BB*LL*LL)      // 204800
#define SCP 321               // padded score row
#define LNQKV_BLOCKS (NROW/RPB)        // 320
#define BIAS_BLOCKS  (NPAIR/64)        // 3200

// ---------------- scratch (allocation-free, device-side references ONLY) ----------------
__device__ float g_q [NROW*DD];
__device__ float g_k [NROW*DD];
__device__ float g_v [NROW*DD];
__device__ float g_bias[NPAIR*NH];     // [b,i,j,h]
__device__ float g_attn[NROW*DD];
__device__ float g_p1[NROW*DO];
__device__ float g_p2[NROW*DO];
__device__ float g_A [NROW*DO*DP];     // [row, d, p]

__device__ __forceinline__ float warp_sum(float v) {
    #pragma unroll
    for (int o = 16; o; o >>= 1) v += __shfl_xor_sync(0xffffffffu, v, o);
    return v;
}
__device__ __forceinline__ float warp_max(float v) {
    #pragma unroll
    for (int o = 16; o; o >>= 1) v = fmaxf(v, __shfl_xor_sync(0xffffffffu, v, o));
    return v;
}

// ---------------- fused input kernel: ln1+QKV blocks ∥ bias blocks ----------------
__global__ void __launch_bounds__(512)
input_kernel(const float* __restrict__ x,
             const float* __restrict__ lg, const float* __restrict__ lb,
             const float* __restrict__ Wq, const float* __restrict__ Wk,
             const float* __restrict__ Wv,
             const float* __restrict__ z, const float* __restrict__ Wb) {
    int t = threadIdx.x;                 // 512
    if (blockIdx.x < LNQKV_BLOCKS) {
        // ======== ln1 + QKV: 2 rows ========
        int r0 = blockIdx.x * RPB;
        __shared__ float xs[RPB][DD];
        __shared__ float r1[RPB][4], r2[RPB][4];
        if (t < RPB*DD) {
            int rr = t >> 7, cc = t & 127;
            float v = x[(r0 + rr)*DD + cc];
            float s = warp_sum(v);
            if ((t & 31) == 0) r1[rr][(cc >> 5)] = s;
            __syncwarp();
            xs[rr][cc] = v;
        }
        __syncthreads();
        if (t < RPB*DD) {
            int rr = t >> 7, cc = t & 127;
            float mu = (r1[rr][0] + r1[rr][1] + r1[rr][2] + r1[rr][3]) * (1.f/128.f);
            float d = xs[rr][cc] - mu;
            float sq = warp_sum(d*d);
            if ((t & 31) == 0) r2[rr][(cc >> 5)] = sq;
        }
        __syncthreads();
        if (t < RPB*DD) {
            int rr = t >> 7, cc = t & 127;
            float mu = (r1[rr][0] + r1[rr][1] + r1[rr][2] + r1[rr][3]) * (1.f/128.f);
            float var = (r2[rr][0] + r2[rr][1] + r2[rr][2] + r2[rr][3]) * (1.f/128.f);
            xs[rr][cc] = (xs[rr][cc] - mu) * rsqrtf(var + 1e-5f) * lg[cc] + lb[cc];
        }
        __syncthreads();
        if (t < 384) {
            int which = t >> 7, c = t & 127;   // 0=q, 1=k, 2=v
            const float* W = (which == 0) ? Wq : ((which == 1) ? Wk : Wv);
            float* outp    = (which == 0) ? g_q : ((which == 1) ? g_k : g_v);
            float acc[RPB] = {0.f, 0.f};
            #pragma unroll 4
            for (int kk = 0; kk < DD; kk++) {
                float wv = W[kk*DD + c];
                #pragma unroll
                for (int r = 0; r < RPB; r++) acc[r] = fmaf(xs[r][kk], wv, acc[r]);
            }
            #pragma unroll
            for (int r = 0; r < RPB; r++) outp[(r0 + r)*DD + c] = acc[r];
        }
    } else {
        // ======== bias: 64 pairs, one (pair,h) output per thread ========
        int bb = blockIdx.x - LNQKV_BLOCKS;
        __shared__ __align__(16) float zs[64][68];   // 64 pairs x 64 (+4 pad)
        __shared__ float wbs[DP][NH];                // [p][h]
        wbs[t >> 3][t & 7] = Wb[t];                  // 512 entries, 512 threads
        size_t base = (size_t)bb * 64 * DP;
        const float4* zsrc = (const float4*)(z + base);
        #pragma unroll
        for (int i = 0; i < 2; i++) {
            int idx = t + i*512;                     // 0..1023 float4s
            int pair = idx >> 4, c4 = idx & 15;
            *((float4*)&zs[pair][c4*4]) = zsrc[idx];
        }
        __syncthreads();
        int pair = t >> 3, h = t & 7;
        float a0 = 0.f, a1 = 0.f;
        #pragma unroll
        for (int p = 0; p < DP; p += 2) {
            a0 = fmaf(zs[pair][p],   wbs[p][h],   a0);
            a1 = fmaf(zs[pair][p+1], wbs[p+1][h], a1);
        }
        g_bias[(size_t)bb * 512 + t] = a0 + a1;      // coalesced [pair][h]
    }
}

// ---------------- attention: one block per (b,i), V tiled via SMEM ----------------
__global__ void attn_kernel() {
    int bi = blockIdx.x;
    int b = bi / LL;
    int t = threadIdx.x;            // 256
    __shared__ float qs[DD];
    __shared__ float sc[NH*SCP];
    __shared__ float vs[32*DD];
    __shared__ float part[DD];
    if (t < DD) qs[t] = g_q[bi*DD + t];
    __syncthreads();
    for (int idx = t; idx < NH*LL; idx += 256) {
        int h = idx / LL, j = idx - h*LL;
        const float4* kp = (const float4*)(g_k + ((size_t)(b*LL + j))*DD + h*DH);
        const float4* qp = (const float4*)(qs + h*DH);
        float acc = 0.f;
        #pragma unroll
        for (int d4 = 0; d4 < 4; d4++) {
            float4 kv = kp[d4], qv = qp[d4];
            acc = fmaf(qv.x, kv.x, acc);
            acc = fmaf(qv.y, kv.y, acc);
            acc = fmaf(qv.z, kv.z, acc);
            acc = fmaf(qv.w, kv.w, acc);
        }
        sc[h*SCP + j] = acc * 0.25f + g_bias[((size_t)bi*LL + j)*NH + h];
    }
    __syncthreads();
    int w = t >> 5, lane = t & 31;
    float m = -INFINITY;
    for (int j = lane; j < LL; j += 32) m = fmaxf(m, sc[w*SCP + j]);
    m = warp_max(m);
    float s = 0.f;
    for (int j = lane; j < LL; j += 32) {
        float e = __expf(sc[w*SCP + j] - m);
        sc[w*SCP + j] = e;
        s += e;
    }
    s = warp_sum(s);
    float inv = 1.f / s;
    for (int j = lane; j < LL; j += 32) sc[w*SCP + j] *= inv;
    __syncthreads();
    int c = t & 127, half = t >> 7;
    int h = c >> 4;
    float acc = 0.f;
    int jb = half * 16;
    for (int j0 = 0; j0 < LL; j0 += 32) {
        const float4* vsrc = (const float4*)(g_v + ((size_t)(b*LL + j0))*DD);
        float4* vdst = (float4*)vs;
        #pragma unroll
        for (int i = 0; i < 4; i++) vdst[t + i*256] = vsrc[t + i*256];
        __syncthreads();
        #pragma unroll
        for (int jj = 0; jj < 16; jj++)
            acc = fmaf(sc[h*SCP + j0 + jb + jj], vs[(jb + jj)*DD + c], acc);
        __syncthreads();
    }
    if (half == 1) part[c] = acc;
    __syncthreads();
    if (half == 0) g_attn[bi*DD + c] = acc + part[c];
}

// ---------------- mega row kernel: proj + ln2 + ffn1 + ffn2 + pproj ----------------
// (round-12 proven version: smem-staged weights, scalar LDS reads)
__global__ void __launch_bounds__(512)
mega_row_kernel(const float* __restrict__ x,
                const float* __restrict__ Wo, const float* __restrict__ bo,
                const float* __restrict__ lg2, const float* __restrict__ lb2,
                const float* __restrict__ W1, const float* __restrict__ b1,
                const float* __restrict__ W2, const float* __restrict__ b2,
                float* __restrict__ out_x,
                const float* __restrict__ Wp1, const float* __restrict__ bp1,
                const float* __restrict__ Wp2, const float* __restrict__ bp2) {
    int r0 = blockIdx.x * RPB;
    int t = threadIdx.x;   // 512
    __shared__ float as[RPB][DD];
    __shared__ float xs[RPB][DD];
    __shared__ float vres[RPB][DD];
    __shared__ float hs[RPB][512];
    __shared__ float part[4][RPB][DD];
    __shared__ float r1[RPB][4], r2[RPB][4];
    __shared__ __align__(16) float ws[8192];    // 32 KB weight tile

    if (t < RPB*DD) { int rr = t >> 7, cc = t & 127; as[rr][cc] = g_attn[(r0 + rr)*DD + cc]; }
    __syncthreads();

    int c = t & 127, ks = t >> 7;            // ks 0..3

    {
        float acc[RPB] = {0.f, 0.f};
        for (int kt = 0; kt < DD; kt += 64) {
            const float4* src = (const float4*)(Wo + kt*DD);
            float4* dst = (float4*)ws;
            #pragma unroll
            for (int i = 0; i < 4; i++) dst[t + i*512] = src[t + i*512];
            __syncthreads();
            int k0 = ks*16;
            #pragma unroll
            for (int kk = 0; kk < 16; kk++) {
                float wv = ws[(k0+kk)*DD + c];
                #pragma unroll
                for (int r = 0; r < RPB; r++) acc[r] = fmaf(as[r][kt+k0+kk], wv, acc[r]);
            }
            __syncthreads();
        }
        #pragma unroll
        for (int r = 0; r < RPB; r++) part[ks][r][c] = acc[r];
    }
    __syncthreads();

    if (t < RPB*DD) {
        int rr = t >> 7, cc = t & 127;
        float v = x[(r0+rr)*DD + cc] + part[0][rr][cc] + part[1][rr][cc]
                + part[2][rr][cc] + part[3][rr][cc] + bo[cc];
        vres[rr][cc] = v;
        float s = warp_sum(v);
        if ((t & 31) == 0) r1[rr][cc >> 5] = s;
    }
    __syncthreads();
    if (t < RPB*DD) {
        int rr = t >> 7, cc = t & 127;
        float mu = (r1[rr][0] + r1[rr][1] + r1[rr][2] + r1[rr][3]) * (1.f/128.f);
        float d = vres[rr][cc] - mu;
        float sq = warp_sum(d*d);
        if ((t & 31) == 0) r2[rr][cc >> 5] = sq;
    }
    __syncthreads();
    if (t < RPB*DD) {
        int rr = t >> 7, cc = t & 127;
        float mu = (r1[rr][0] + r1[rr][1] + r1[rr][2] + r1[rr][3]) * (1.f/128.f);
        float var = (r2[rr][0] + r2[rr][1] + r2[rr][2] + r2[rr][3]) * (1.f/128.f);
        xs[rr][cc] = (vres[rr][cc] - mu) * rsqrtf(var + 1e-5f) * lg2[cc] + lb2[cc];
    }
    __syncthreads();

    {
        float acc[RPB] = {0.f, 0.f};
        for (int kt = 0; kt < DD; kt += 16) {
            const float4* src = (const float4*)(W1 + kt*512);
            float4* dst = (float4*)ws;
            #pragma unroll
            for (int i = 0; i < 4; i++) dst[t + i*512] = src[t + i*512];
            __syncthreads();
            #pragma unroll
            for (int kk = 0; kk < 16; kk++) {
                float wv = ws[kk*512 + t];
                #pragma unroll
                for (int r = 0; r < RPB; r++) acc[r] = fmaf(xs[r][kt+kk], wv, acc[r]);
            }
            __syncthreads();
        }
        float bb = b1[t];
        #pragma unroll
        for (int r = 0; r < RPB; r++) {
            float hv = acc[r] + bb;
            hs[r][t] = 0.5f * hv * (1.f + erff(hv * 0.70710678118654752f));
        }
    }
    __syncthreads();

    {
        float acc[RPB] = {0.f, 0.f};
        for (int kt = 0; kt < 512; kt += 64) {
            const float4* src = (const float4*)(W2 + kt*DD);
            float4* dst = (float4*)ws;
            #pragma unroll
            for (int i = 0; i < 4; i++) dst[t + i*512] = src[t + i*512];
            __syncthreads();
            int k0 = ks*16;
            #pragma unroll
            for (int kk = 0; kk < 16; kk++) {
                float wv = ws[(k0+kk)*DD + c];
                #pragma unroll
                for (int r = 0; r < RPB; r++) acc[r] = fmaf(hs[r][kt+k0+kk], wv, acc[r]);
            }
            __syncthreads();
        }
        #pragma unroll
        for (int r = 0; r < RPB; r++) part[ks][r][c] = acc[r];
    }
    __syncthreads();
    if (t < RPB*DD) {
        int rr = t >> 7, cc = t & 127;
        float xv = vres[rr][cc] + part[0][rr][cc] + part[1][rr][cc]
                 + part[2][rr][cc] + part[3][rr][cc] + b2[cc];
        out_x[(r0+rr)*DD + cc] = xv;
        xs[rr][cc] = xv;
    }
    __syncthreads();

    if (t < 256) {
        int o  = t & 63;
        int sl = t >> 6;
        const float* W = (o < 32) ? Wp1 : Wp2;
        int col = o & 31;
        int k0 = sl*32;
        float acc[RPB] = {0.f, 0.f};
        #pragma unroll
        for (int kk = 0; kk < 32; kk++) {
            float wv = W[(k0+kk)*DO + col];
            #pragma unroll
            for (int r = 0; r < RPB; r++) acc[r] = fmaf(xs[r][k0+kk], wv, acc[r]);
        }
        #pragma unroll
        for (int r = 0; r < RPB; r++) part[sl][r][o] = acc[r];
    }
    __syncthreads();
    if (t < RPB*64) {
        int r = t >> 6, o = t & 63;
        float sum = part[0][r][o] + part[1][r][o] + part[2][r][o] + part[3][r][o];
        if (o < 32) g_p1[(r0+r)*DO + o]        = sum + bp1[o];
        else        g_p2[(r0+r)*DO + (o - 32)] = sum + bp2[o - 32];
    }
}

// ---------------- A[row, d, p]: grid = (NROW/4) x 4 dp-chunks for occupancy ----------------
__global__ void a_kernel(const float* __restrict__ Wz) {
    int blk = blockIdx.x;
    int r0  = (blk >> 2) * 4;          // 4 rows
    int dp0 = (blk & 3) * 512;         // 512-wide dp chunk
    int t = threadIdx.x;               // 256
    __shared__ float p1s[4][DO];
    if (t < 128) { int r = t >> 5, c = t & 31; p1s[r][c] = g_p1[(r0 + r)*DO + c]; }
    __syncthreads();
    #pragma unroll
    for (int i = 0; i < 2; i++) {
        int dp = dp0 + t + i*256;
        float acc[4] = {0,0,0,0};
        #pragma unroll 8
        for (int c = 0; c < DO; c++) {
            float wv = Wz[(size_t)c*(DO*DP) + dp];
            #pragma unroll
            for (int r = 0; r < 4; r++) acc[r] = fmaf(p1s[r][c], wv, acc[r]);
        }
        #pragma unroll
        for (int r = 0; r < 4; r++) g_A[(size_t)(r0 + r)*(DO*DP) + dp] = acc[r];
    }
}

// ---------------- final: z_out = LN(z + A(i)·p2(j) + bz), single j-row per warp iter ----------------
__global__ void __launch_bounds__(256, 2)
pair_final_kernel(const float* __restrict__ z, const float* __restrict__ bz,
                  const float* __restrict__ g, const float* __restrict__ be,
                  float* __restrict__ zout) {
    int bi = blockIdx.x;
    int b = bi / LL;
    int t = threadIdx.x, w = t >> 5, lane = t & 31;
    __shared__ __align__(16) float p2s[64][DO];   // 8 KB tile
    const float2* Ag = (const float2*)(g_A + (size_t)bi*(DO*DP));
    float2 a[DO];
    #pragma unroll
    for (int d = 0; d < DO; d++) a[d] = Ag[d*32 + lane];
    float bz0 = bz[2*lane], bz1 = bz[2*lane + 1];
    float g0 = g[2*lane],  g1 = g[2*lane + 1];
    float e0 = be[2*lane], e1 = be[2*lane + 1];
    size_t zbase = (size_t)bi * LL * DP;
    const float* p2b = g_p2 + (size_t)b * LL * DO;
    for (int jt = 0; jt < LL; jt += 64) {
        const float4* src = (const float4*)(p2b + (size_t)jt * DO);
        float4* dst = (float4*)&p2s[0][0];
        dst[t] = src[t];
        dst[t + 256] = src[t + 256];
        __syncthreads();
        for (int jj = w; jj < 64; jj += 8) {
            int j = jt + jj;
            float2 zv = *(const float2*)(z + zbase + (size_t)j*DP + 2*lane);
            const float4* p4 = (const float4*)&p2s[jj][0];
            float acc0 = 0.f, acc1 = 0.f;
            #pragma unroll
            for (int d4 = 0; d4 < 8; d4++) {
                float4 s4 = p4[d4];
                acc0 = fmaf(s4.x, a[d4*4+0].x, acc0); acc1 = fmaf(s4.x, a[d4*4+0].y, acc1);
                acc0 = fmaf(s4.y, a[d4*4+1].x, acc0); acc1 = fmaf(s4.y, a[d4*4+1].y, acc1);
                acc0 = fmaf(s4.z, a[d4*4+2].x, acc0); acc1 = fmaf(s4.z, a[d4*4+2].y, acc1);
                acc0 = fmaf(s4.w, a[d4*4+3].x, acc0); acc1 = fmaf(s4.w, a[d4*4+3].y, acc1);
            }
            float v0 = zv.x + acc0 + bz0;
            float v1 = zv.y + acc1 + bz1;
            float s1 = warp_sum(v0 + v1);
            float s2 = warp_sum(fmaf(v0, v0, v1*v1));
            float mu = s1 * (1.f/64.f);
            float var = s2 * (1.f/64.f) - mu*mu;
            float rs = rsqrtf(var + 1e-5f);
            float2 o;
            o.x = (v0 - mu) * rs * g0 + e0;
            o.y = (v1 - mu) * rs * g1 + e1;
            *(float2*)(zout + zbase + (size_t)j*DP + 2*lane) = o;
        }
        __syncthreads();
    }
}

extern "C" void kernel_launch(void* const* d_in, const int* in_sizes, int n_in,
                              void* d_out, int out_size) {
    const float* x      = (const float*)d_in[0];
    const float* z      = (const float*)d_in[1];
    const float* Wq     = (const float*)d_in[2];
    const float* Wk     = (const float*)d_in[3];
    const float* Wv     = (const float*)d_in[4];
    const float* Wb     = (const float*)d_in[5];
    const float* Wo     = (const float*)d_in[6];
    const float* bo     = (const float*)d_in[7];
    const float* ln1_g  = (const float*)d_in[8];
    const float* ln1_b  = (const float*)d_in[9];
    const float* W1     = (const float*)d_in[10];
    const float* b1     = (const float*)d_in[11];
    const float* W2     = (const float*)d_in[12];
    const float* b2     = (const float*)d_in[13];
    const float* ln2_g  = (const float*)d_in[14];
    const float* ln2_b  = (const float*)d_in[15];
    const float* Wp1    = (const float*)d_in[16];
    const float* bp1    = (const float*)d_in[17];
    const float* Wp2    = (const float*)d_in[18];
    const float* bp2    = (const float*)d_in[19];
    const float* Wz     = (const float*)d_in[20];
    const float* bz     = (const float*)d_in[21];
    const float* lnp_g  = (const float*)d_in[22];
    const float* lnp_b  = (const float*)d_in[23];

    float* out_x = (float*)d_out;                       // [B,L,D]
    float* out_z = (float*)d_out + (size_t)NROW*DD;     // [B,L,L,DP]

    input_kernel<<<LNQKV_BLOCKS + BIAS_BLOCKS, 512>>>(x, ln1_g, ln1_b, Wq, Wk, Wv, z, Wb);
    attn_kernel<<<NROW, 256>>>();
    mega_row_kernel<<<NROW/RPB, 512>>>(x, Wo, bo, ln2_g, ln2_b, W1, b1, W2, b2,
                                       out_x, Wp1, bp1, Wp2, bp2);
    a_kernel<<<(NROW/4)*4, 256>>>(Wz);
    pair_final_kernel<<<NROW, 256>>>(z, bz, lnp_g, lnp_b, out_z);
}

// round 16
// speedup vs baseline: 1.1106x; 1.0068x over previous
#include <cuda_runtime.h>
#include <math.h>

#define BB 2
#define LL 320
#define DD 128
#define DP 64
#define NH 8
#define DH 16
#define DO 32
#define RPB 2                 // rows per block for row-fused kernels
#define NROW (BB*LL)          // 640
#define NPAIR (BB*LL*LL)      // 204800
#define SCP 321               // padded score row
#define LNQKV_BLOCKS (NROW/RPB)        // 320
#define BIAS_BLOCKS  (NPAIR/64)        // 3200

// ---------------- scratch (allocation-free, device-side references ONLY) ----------------
__device__ float g_q [NROW*DD];
__device__ float g_k [NROW*DD];
__device__ float g_v [NROW*DD];
__device__ float g_bias[NPAIR*NH];     // [b,i,j,h]
__device__ float g_attn[NROW*DD];
__device__ float g_p1[NROW*DO];
__device__ float g_p2[NROW*DO];

__device__ __forceinline__ float warp_sum(float v) {
    #pragma unroll
    for (int o = 16; o; o >>= 1) v += __shfl_xor_sync(0xffffffffu, v, o);
    return v;
}
__device__ __forceinline__ float warp_max(float v) {
    #pragma unroll
    for (int o = 16; o; o >>= 1) v = fmaxf(v, __shfl_xor_sync(0xffffffffu, v, o));
    return v;
}

// ---------------- fused input kernel: ln1+QKV blocks ∥ bias blocks ----------------
__global__ void __launch_bounds__(512)
input_kernel(const float* __restrict__ x,
             const float* __restrict__ lg, const float* __restrict__ lb,
             const float* __restrict__ Wq, const float* __restrict__ Wk,
             const float* __restrict__ Wv,
             const float* __restrict__ z, const float* __restrict__ Wb) {
    int t = threadIdx.x;                 // 512
    if (blockIdx.x < LNQKV_BLOCKS) {
        // ======== ln1 + QKV: 2 rows ========
        int r0 = blockIdx.x * RPB;
        __shared__ float xs[RPB][DD];
        __shared__ float r1[RPB][4], r2[RPB][4];
        if (t < RPB*DD) {
            int rr = t >> 7, cc = t & 127;
            float v = x[(r0 + rr)*DD + cc];
            float s = warp_sum(v);
            if ((t & 31) == 0) r1[rr][(cc >> 5)] = s;
            __syncwarp();
            xs[rr][cc] = v;
        }
        __syncthreads();
        if (t < RPB*DD) {
            int rr = t >> 7, cc = t & 127;
            float mu = (r1[rr][0] + r1[rr][1] + r1[rr][2] + r1[rr][3]) * (1.f/128.f);
            float d = xs[rr][cc] - mu;
            float sq = warp_sum(d*d);
            if ((t & 31) == 0) r2[rr][(cc >> 5)] = sq;
        }
        __syncthreads();
        if (t < RPB*DD) {
            int rr = t >> 7, cc = t & 127;
            float mu = (r1[rr][0] + r1[rr][1] + r1[rr][2] + r1[rr][3]) * (1.f/128.f);
            float var = (r2[rr][0] + r2[rr][1] + r2[rr][2] + r2[rr][3]) * (1.f/128.f);
            xs[rr][cc] = (xs[rr][cc] - mu) * rsqrtf(var + 1e-5f) * lg[cc] + lb[cc];
        }
        __syncthreads();
        if (t < 384) {
            int which = t >> 7, c = t & 127;   // 0=q, 1=k, 2=v
            const float* W = (which == 0) ? Wq : ((which == 1) ? Wk : Wv);
            float* outp    = (which == 0) ? g_q : ((which == 1) ? g_k : g_v);
            float acc[RPB] = {0.f, 0.f};
            #pragma unroll 4
            for (int kk = 0; kk < DD; kk++) {
                float wv = W[kk*DD + c];
                #pragma unroll
                for (int r = 0; r < RPB; r++) acc[r] = fmaf(xs[r][kk], wv, acc[r]);
            }
            #pragma unroll
            for (int r = 0; r < RPB; r++) outp[(r0 + r)*DD + c] = acc[r];
        }
    } else {
        // ======== bias: 64 pairs, one (pair,h) output per thread ========
        int bb = blockIdx.x - LNQKV_BLOCKS;
        __shared__ __align__(16) float zs[64][68];   // 64 pairs x 64 (+4 pad)
        __shared__ float wbs[DP][NH];                // [p][h]
        wbs[t >> 3][t & 7] = Wb[t];                  // 512 entries, 512 threads
        size_t base = (size_t)bb * 64 * DP;
        const float4* zsrc = (const float4*)(z + base);
        #pragma unroll
        for (int i = 0; i < 2; i++) {
            int idx = t + i*512;                     // 0..1023 float4s
            int pair = idx >> 4, c4 = idx & 15;
            *((float4*)&zs[pair][c4*4]) = zsrc[idx];
        }
        __syncthreads();
        int pair = t >> 3, h = t & 7;
        float a0 = 0.f, a1 = 0.f;
        #pragma unroll
        for (int p = 0; p < DP; p += 2) {
            a0 = fmaf(zs[pair][p],   wbs[p][h],   a0);
            a1 = fmaf(zs[pair][p+1], wbs[p+1][h], a1);
        }
        g_bias[(size_t)bb * 512 + t] = a0 + a1;      // coalesced [pair][h]
    }
}

// ---------------- attention: one block per (b,i), V tiled via SMEM ----------------
__global__ void attn_kernel() {
    int bi = blockIdx.x;
    int b = bi / LL;
    int t = threadIdx.x;            // 256
    __shared__ float qs[DD];
    __shared__ float sc[NH*SCP];
    __shared__ float vs[32*DD];
    __shared__ float part[DD];
    if (t < DD) qs[t] = g_q[bi*DD + t];
    __syncthreads();
    for (int idx = t; idx < NH*LL; idx += 256) {
        int h = idx / LL, j = idx - h*LL;
        const float4* kp = (const float4*)(g_k + ((size_t)(b*LL + j))*DD + h*DH);
        const float4* qp = (const float4*)(qs + h*DH);
        float acc = 0.f;
        #pragma unroll
        for (int d4 = 0; d4 < 4; d4++) {
            float4 kv = kp[d4], qv = qp[d4];
            acc = fmaf(qv.x, kv.x, acc);
            acc = fmaf(qv.y, kv.y, acc);
            acc = fmaf(qv.z, kv.z, acc);
            acc = fmaf(qv.w, kv.w, acc);
        }
        sc[h*SCP + j] = acc * 0.25f + g_bias[((size_t)bi*LL + j)*NH + h];
    }
    __syncthreads();
    int w = t >> 5, lane = t & 31;
    float m = -INFINITY;
    for (int j = lane; j < LL; j += 32) m = fmaxf(m, sc[w*SCP + j]);
    m = warp_max(m);
    float s = 0.f;
    for (int j = lane; j < LL; j += 32) {
        float e = __expf(sc[w*SCP + j] - m);
        sc[w*SCP + j] = e;
        s += e;
    }
    s = warp_sum(s);
    float inv = 1.f / s;
    for (int j = lane; j < LL; j += 32) sc[w*SCP + j] *= inv;
    __syncthreads();
    int c = t & 127, half = t >> 7;
    int h = c >> 4;
    float acc = 0.f;
    int jb = half * 16;
    for (int j0 = 0; j0 < LL; j0 += 32) {
        const float4* vsrc = (const float4*)(g_v + ((size_t)(b*LL + j0))*DD);
        float4* vdst = (float4*)vs;
        #pragma unroll
        for (int i = 0; i < 4; i++) vdst[t + i*256] = vsrc[t + i*256];
        __syncthreads();
        #pragma unroll
        for (int jj = 0; jj < 16; jj++)
            acc = fmaf(sc[h*SCP + j0 + jb + jj], vs[(jb + jj)*DD + c], acc);
        __syncthreads();
    }
    if (half == 1) part[c] = acc;
    __syncthreads();
    if (half == 0) g_attn[bi*DD + c] = acc + part[c];
}

// ---------------- mega row kernel: proj + ln2 + ffn1 + ffn2 + pproj ----------------
__global__ void __launch_bounds__(512)
mega_row_kernel(const float* __restrict__ x,
                const float* __restrict__ Wo, const float* __restrict__ bo,
                const float* __restrict__ lg2, const float* __restrict__ lb2,
                const float* __restrict__ W1, const float* __restrict__ b1,
                const float* __restrict__ W2, const float* __restrict__ b2,
                float* __restrict__ out_x,
                const float* __restrict__ Wp1, const float* __restrict__ bp1,
                const float* __restrict__ Wp2, const float* __restrict__ bp2) {
    int r0 = blockIdx.x * RPB;
    int t = threadIdx.x;   // 512
    __shared__ float as[RPB][DD];
    __shared__ float xs[RPB][DD];
    __shared__ float vres[RPB][DD];
    __shared__ float hs[RPB][512];
    __shared__ float part[4][RPB][DD];
    __shared__ float r1[RPB][4], r2[RPB][4];
    __shared__ __align__(16) float ws[8192];    // 32 KB weight tile

    if (t < RPB*DD) { int rr = t >> 7, cc = t & 127; as[rr][cc] = g_attn[(r0 + rr)*DD + cc]; }
    __syncthreads();

    int c = t & 127, ks = t >> 7;            // ks 0..3

    {
        float acc[RPB] = {0.f, 0.f};
        for (int kt = 0; kt < DD; kt += 64) {
            const float4* src = (const float4*)(Wo + kt*DD);
            float4* dst = (float4*)ws;
            #pragma unroll
            for (int i = 0; i < 4; i++) dst[t + i*512] = src[t + i*512];
            __syncthreads();
            int k0 = ks*16;
            #pragma unroll
            for (int kk = 0; kk < 16; kk++) {
                float wv = ws[(k0+kk)*DD + c];
                #pragma unroll
                for (int r = 0; r < RPB; r++) acc[r] = fmaf(as[r][kt+k0+kk], wv, acc[r]);
            }
            __syncthreads();
        }
        #pragma unroll
        for (int r = 0; r < RPB; r++) part[ks][r][c] = acc[r];
    }
    __syncthreads();

    if (t < RPB*DD) {
        int rr = t >> 7, cc = t & 127;
        float v = x[(r0+rr)*DD + cc] + part[0][rr][cc] + part[1][rr][cc]
                + part[2][rr][cc] + part[3][rr][cc] + bo[cc];
        vres[rr][cc] = v;
        float s = warp_sum(v);
        if ((t & 31) == 0) r1[rr][cc >> 5] = s;
    }
    __syncthreads();
    if (t < RPB*DD) {
        int rr = t >> 7, cc = t & 127;
        float mu = (r1[rr][0] + r1[rr][1] + r1[rr][2] + r1[rr][3]) * (1.f/128.f);
        float d = vres[rr][cc] - mu;
        float sq = warp_sum(d*d);
        if ((t & 31) == 0) r2[rr][cc >> 5] = sq;
    }
    __syncthreads();
    if (t < RPB*DD) {
        int rr = t >> 7, cc = t & 127;
        float mu = (r1[rr][0] + r1[rr][1] + r1[rr][2] + r1[rr][3]) * (1.f/128.f);
        float var = (r2[rr][0] + r2[rr][1] + r2[rr][2] + r2[rr][3]) * (1.f/128.f);
        xs[rr][cc] = (vres[rr][cc] - mu) * rsqrtf(var + 1e-5f) * lg2[cc] + lb2[cc];
    }
    __syncthreads();

    {
        float acc[RPB] = {0.f, 0.f};
        for (int kt = 0; kt < DD; kt += 16) {
            const float4* src = (const float4*)(W1 + kt*512);
            float4* dst = (float4*)ws;
            #pragma unroll
            for (int i = 0; i < 4; i++) dst[t + i*512] = src[t + i*512];
            __syncthreads();
            #pragma unroll
            for (int kk = 0; kk < 16; kk++) {
                float wv = ws[kk*512 + t];
                #pragma unroll
                for (int r = 0; r < RPB; r++) acc[r] = fmaf(xs[r][kt+kk], wv, acc[r]);
            }
            __syncthreads();
        }
        float bb = b1[t];
        #pragma unroll
        for (int r = 0; r < RPB; r++) {
            float hv = acc[r] + bb;
            hs[r][t] = 0.5f * hv * (1.f + erff(hv * 0.70710678118654752f));
        }
    }
    __syncthreads();

    {
        float acc[RPB] = {0.f, 0.f};
        for (int kt = 0; kt < 512; kt += 64) {
            const float4* src = (const float4*)(W2 + kt*DD);
            float4* dst = (float4*)ws;
            #pragma unroll
            for (int i = 0; i < 4; i++) dst[t + i*512] = src[t + i*512];
            __syncthreads();
            int k0 = ks*16;
            #pragma unroll
            for (int kk = 0; kk < 16; kk++) {
                float wv = ws[(k0+kk)*DD + c];
                #pragma unroll
                for (int r = 0; r < RPB; r++) acc[r] = fmaf(hs[r][kt+k0+kk], wv, acc[r]);
            }
            __syncthreads();
        }
        #pragma unroll
        for (int r = 0; r < RPB; r++) part[ks][r][c] = acc[r];
    }
    __syncthreads();
    if (t < RPB*DD) {
        int rr = t >> 7, cc = t & 127;
        float xv = vres[rr][cc] + part[0][rr][cc] + part[1][rr][cc]
                 + part[2][rr][cc] + part[3][rr][cc] + b2[cc];
        out_x[(r0+rr)*DD + cc] = xv;
        xs[rr][cc] = xv;
    }
    __syncthreads();

    if (t < 256) {
        int o  = t & 63;
        int sl = t >> 6;
        const float* W = (o < 32) ? Wp1 : Wp2;
        int col = o & 31;
        int k0 = sl*32;
        float acc[RPB] = {0.f, 0.f};
        #pragma unroll
        for (int kk = 0; kk < 32; kk++) {
            float wv = W[(k0+kk)*DO + col];
            #pragma unroll
            for (int r = 0; r < RPB; r++) acc[r] = fmaf(xs[r][k0+kk], wv, acc[r]);
        }
        #pragma unroll
        for (int r = 0; r < RPB; r++) part[sl][r][o] = acc[r];
    }
    __syncthreads();
    if (t < RPB*64) {
        int r = t >> 6, o = t & 63;
        float sum = part[0][r][o] + part[1][r][o] + part[2][r][o] + part[3][r][o];
        if (o < 32) g_p1[(r0+r)*DO + o]        = sum + bp1[o];
        else        g_p2[(r0+r)*DO + (o - 32)] = sum + bp2[o - 32];
    }
}

// ---------------- final: A computed in-block, then z_out = LN(z + A·p2 + bz) ----------------
__global__ void __launch_bounds__(256, 2)
pair_final_kernel(const float* __restrict__ z, const float* __restrict__ Wz,
                  const float* __restrict__ bz,
                  const float* __restrict__ g, const float* __restrict__ be,
                  float* __restrict__ zout) {
    int bi = blockIdx.x;
    int b = bi / LL;
    int t = threadIdx.x, w = t >> 5, lane = t & 31;
    __shared__ __align__(16) float p2s[64][DO];   // 8 KB tile
    __shared__ __align__(16) float A_s[DO*DP];    // 8 KB: A[d*64 + p]
    __shared__ float p1s[DO];

    if (t < DO) p1s[t] = g_p1[bi*DO + t];
    __syncthreads();
    // prelude: A[dp] = sum_c p1[c] * Wz[c*2048 + dp]; each thread covers 8 dp, coalesced
    {
        float acc[8] = {0,0,0,0,0,0,0,0};
        for (int c = 0; c < DO; c++) {
            float pv = p1s[c];
            const float* wr = Wz + (size_t)c * (DO*DP);
            #pragma unroll
            for (int i = 0; i < 8; i++)
                acc[i] = fmaf(pv, wr[t + 256*i], acc[i]);
        }
        #pragma unroll
        for (int i = 0; i < 8; i++) A_s[t + 256*i] = acc[i];
    }
    __syncthreads();

    float2 a[DO];
    #pragma unroll
    for (int d = 0; d < DO; d++) a[d] = *(const float2*)&A_s[d*DP + 2*lane];
    float bz0 = bz[2*lane], bz1 = bz[2*lane + 1];
    float g0 = g[2*lane],  g1 = g[2*lane + 1];
    float e0 = be[2*lane], e1 = be[2*lane + 1];
    size_t zbase = (size_t)bi * LL * DP;
    const float* p2b = g_p2 + (size_t)b * LL * DO;
    for (int jt = 0; jt < LL; jt += 64) {
        const float4* src = (const float4*)(p2b + (size_t)jt * DO);
        float4* dst = (float4*)&p2s[0][0];
        dst[t] = src[t];
        dst[t + 256] = src[t + 256];
        __syncthreads();
        for (int jj = w; jj < 64; jj += 8) {
            int j = jt + jj;
            float2 zv = *(const float2*)(z + zbase + (size_t)j*DP + 2*lane);
            const float4* p4 = (const float4*)&p2s[jj][0];
            float acc0 = 0.f, acc1 = 0.f;
            #pragma unroll
            for (int d4 = 0; d4 < 8; d4++) {
                float4 s4 = p4[d4];
                acc0 = fmaf(s4.x, a[d4*4+0].x, acc0); acc1 = fmaf(s4.x, a[d4*4+0].y, acc1);
                acc0 = fmaf(s4.y, a[d4*4+1].x, acc0); acc1 = fmaf(s4.y, a[d4*4+1].y, acc1);
                acc0 = fmaf(s4.z, a[d4*4+2].x, acc0); acc1 = fmaf(s4.z, a[d4*4+2].y, acc1);
                acc0 = fmaf(s4.w, a[d4*4+3].x, acc0); acc1 = fmaf(s4.w, a[d4*4+3].y, acc1);
            }
            float v0 = zv.x + acc0 + bz0;
            float v1 = zv.y + acc1 + bz1;
            float s1 = warp_sum(v0 + v1);
            float s2 = warp_sum(fmaf(v0, v0, v1*v1));
            float mu = s1 * (1.f/64.f);
            float var = s2 * (1.f/64.f) - mu*mu;
            float rs = rsqrtf(var + 1e-5f);
            float2 o;
            o.x = (v0 - mu) * rs * g0 + e0;
            o.y = (v1 - mu) * rs * g1 + e1;
            *(float2*)(zout + zbase + (size_t)j*DP + 2*lane) = o;
        }
        __syncthreads();
    }
}

extern "C" void kernel_launch(void* const* d_in, const int* in_sizes, int n_in,
                              void* d_out, int out_size) {
    const float* x      = (const float*)d_in[0];
    const float* z      = (const float*)d_in[1];
    const float* Wq     = (const float*)d_in[2];
    const float* Wk     = (const float*)d_in[3];
    const float* Wv     = (const float*)d_in[4];
    const float* Wb     = (const float*)d_in[5];
    const float* Wo     = (const float*)d_in[6];
    const float* bo     = (const float*)d_in[7];
    const float* ln1_g  = (const float*)d_in[8];
    const float* ln1_b  = (const float*)d_in[9];
    const float* W1     = (const float*)d_in[10];
    const float* b1     = (const float*)d_in[11];
    const float* W2     = (const float*)d_in[12];
    const float* b2     = (const float*)d_in[13];
    const float* ln2_g  = (const float*)d_in[14];
    const float* ln2_b  = (const float*)d_in[15];
    const float* Wp1    = (const float*)d_in[16];
    const float* bp1    = (const float*)d_in[17];
    const float* Wp2    = (const float*)d_in[18];
    const float* bp2    = (const float*)d_in[19];
    const float* Wz     = (const float*)d_in[20];
    const float* bz     = (const float*)d_in[21];
    const float* lnp_g  = (const float*)d_in[22];
    const float* lnp_b  = (const float*)d_in[23];

    float* out_x = (float*)d_out;                       // [B,L,D]
    float* out_z = (float*)d_out + (size_t)NROW*DD;     // [B,L,L,DP]

    input_kernel<<<LNQKV_BLOCKS + BIAS_BLOCKS, 512>>>(x, ln1_g, ln1_b, Wq, Wk, Wv, z, Wb);
    attn_kernel<<<NROW, 256>>>();
    mega_row_kernel<<<NROW/RPB, 512>>>(x, Wo, bo, ln2_g, ln2_b, W1, b1, W2, b2,
                                       out_x, Wp1, bp1, Wp2, bp2);
    pair_final_kernel<<<NROW, 256>>>(z, Wz, bz, lnp_g, lnp_b, out_z);
}